// round 13
// baseline (speedup 1.0000x reference)
#include <cuda_runtime.h>
#include <math.h>

#define Bz 256
#define Sz 256
#define Mz 50
#define WST 64          // g_w row stride: 32 pairs (25 real + 7 zero pad)
#define DQz 64
#define DVz 128
#define Fz 128
#define NQ1 10001
#define NQA1 20001
#define NROWS (Bz*Sz)

typedef unsigned long long u64;

// ---- packed f32x2 helpers ---------------------------------------------------
__device__ __forceinline__ u64 pack2(float lo, float hi) {
    u64 r; asm("mov.b64 %0, {%1, %2};" : "=l"(r) : "f"(lo), "f"(hi)); return r;
}
__device__ __forceinline__ void unpack2(u64 v, float& lo, float& hi) {
    asm("mov.b64 {%0, %1}, %2;" : "=f"(lo), "=f"(hi) : "l"(v));
}
__device__ __forceinline__ u64 fma2(u64 a, u64 b, u64 c) {
    u64 d; asm("fma.rn.f32x2 %0, %1, %2, %3;" : "=l"(d) : "l"(a), "l"(b), "l"(c)); return d;
}
__device__ __forceinline__ u64 add2(u64 a, u64 b) {
    u64 d; asm("add.rn.f32x2 %0, %1, %2;" : "=l"(d) : "l"(a), "l"(b)); return d;
}

// ---- tf32 mma helpers ---------------------------------------------------------
__device__ __forceinline__ float f2tf(float f) {
    unsigned r; asm("cvt.rna.tf32.f32 %0, %1;" : "=r"(r) : "f"(f));
    return __uint_as_float(r);
}
__device__ __forceinline__ float4 f2tf4(float4 v) {
    return make_float4(f2tf(v.x), f2tf(v.y), f2tf(v.z), f2tf(v.w));
}
__device__ __forceinline__ void mma8(float* d, const unsigned* a, const unsigned* b) {
    asm volatile(
        "mma.sync.aligned.m16n8k8.row.col.f32.tf32.tf32.f32 "
        "{%0,%1,%2,%3}, {%4,%5,%6,%7}, {%8,%9}, {%0,%1,%2,%3};"
        : "+f"(d[0]), "+f"(d[1]), "+f"(d[2]), "+f"(d[3])
        : "r"(a[0]), "r"(a[1]), "r"(a[2]), "r"(a[3]), "r"(b[0]), "r"(b[1]));
}

// Scratch
__device__ float  g_w[NQ1 * WST];
__device__ float2 g_ea[NQA1 * DVz];
__device__ float  g_qr[NQ1 * Fz];
__device__ float  g_reads[NROWS * DVz];
__device__ float  g_acc[2];
__device__ int    g_done;

// ---------------------------------------------------------------------------
__global__ void __launch_bounds__(128) k_w(const float* __restrict__ q_table,
                                           const float* __restrict__ key_mem) {
    __shared__ float key_s[Mz * DQz];
    int tid = threadIdx.x;
    if (blockIdx.x == 0 && tid < 3) {
        if (tid < 2) g_acc[tid] = 0.0f;
        else g_done = 0;
    }
    for (int i = tid; i < Mz * DQz; i += 128) key_s[i] = key_mem[i];
    __syncthreads();

    int row = blockIdx.x * 128 + tid;
    if (row >= NQ1) return;

    float q[DQz];
    const float4* qp = (const float4*)(q_table + (long)row * DQz);
#pragma unroll
    for (int i = 0; i < DQz / 4; i++) {
        float4 v = qp[i];
        q[4*i+0] = v.x; q[4*i+1] = v.y; q[4*i+2] = v.z; q[4*i+3] = v.w;
    }

    float sc[Mz];
    float mx = -1e30f;
#pragma unroll
    for (int m = 0; m < Mz; m++) {
        float s = 0.0f;
#pragma unroll
        for (int k = 0; k < DQz; k++) s = fmaf(q[k], key_s[m * DQz + k], s);
        sc[m] = s;
        mx = fmaxf(mx, s);
    }
    float sum = 0.0f;
#pragma unroll
    for (int m = 0; m < Mz; m++) {
        float e = __expf(sc[m] - mx);
        sc[m] = e;
        sum += e;
    }
    float inv = 1.0f / sum;
#pragma unroll
    for (int m = 0; m < Mz; m++) g_w[row * WST + m] = sc[m] * inv;
#pragma unroll
    for (int m = Mz; m < WST; m++) g_w[row * WST + m] = 0.0f;
}

// ---------------------------------------------------------------------------
#define QR_ROWS 64
#define QR_SMEM_FLOATS (64*128 + QR_ROWS*DQz)
__global__ void __launch_bounds__(512) k_qr(const float* __restrict__ q_table,
                                            const float* __restrict__ W_read) {
    extern __shared__ float sm[];
    float* W2 = sm;
    float* xs = W2 + 64 * 128;

    int tid = threadIdx.x;
    for (int i = tid; i < 64 * 128 / 4; i += 512)
        ((float4*)W2)[i] = ((const float4*)(W_read + 128 * 128))[i];

    int row0 = blockIdx.x * QR_ROWS;
    for (int idx = tid; idx < QR_ROWS * 16; idx += 512) {
        int r = idx >> 4, c = idx & 15;
        int row = row0 + r;
        float4 v = make_float4(0.f, 0.f, 0.f, 0.f);
        if (row < NQ1) v = ((const float4*)(q_table + (long)row * DQz))[c];
        ((float4*)xs)[r * 16 + c] = v;
    }
    __syncthreads();

    int rg = tid >> 4;
    int fg = tid & 15;
    u64 acc[2][4];
#pragma unroll
    for (int r = 0; r < 2; r++)
#pragma unroll
        for (int j = 0; j < 4; j++) acc[r][j] = 0ull;

#pragma unroll 4
    for (int k = 0; k < 64; k++) {
        const ulonglong2* wv = (const ulonglong2*)(W2 + k * 128 + fg * 8);
        ulonglong2 w01 = wv[0], w23 = wv[1];
#pragma unroll
        for (int r = 0; r < 2; r++) {
            float xv = xs[(rg * 2 + r) * DQz + k];
            u64 xp = pack2(xv, xv);
            acc[r][0] = fma2(xp, w01.x, acc[r][0]);
            acc[r][1] = fma2(xp, w01.y, acc[r][1]);
            acc[r][2] = fma2(xp, w23.x, acc[r][2]);
            acc[r][3] = fma2(xp, w23.y, acc[r][3]);
        }
    }

#pragma unroll
    for (int r = 0; r < 2; r++) {
        int row = row0 + rg * 2 + r;
        if (row < NQ1) {
            float v[8];
#pragma unroll
            for (int j = 0; j < 4; j++) unpack2(acc[r][j], v[2*j], v[2*j+1]);
            float4* op = (float4*)(g_qr + (long)row * Fz + fg * 8);
            op[0] = make_float4(v[0], v[1], v[2], v[3]);
            op[1] = make_float4(v[4], v[5], v[6], v[7]);
        }
    }
}

// ---------------------------------------------------------------------------
// ea via tf32 mma (R12, unchanged). 128 rows/block, 512 thr, grid 157.
#define EA_XS_STRIDE 132
#define EA_WB_STRIDE 264
#define EA_SMEM_FLOATS (128*EA_WB_STRIDE + 128*EA_XS_STRIDE + 256)
__global__ void __launch_bounds__(512) k_ea(const float* __restrict__ qa_table,
                     const float* __restrict__ W_e, const float* __restrict__ b_e,
                     const float* __restrict__ W_a, const float* __restrict__ b_a) {
    extern __shared__ float sm[];
    float* Wb = sm;                          // [128 k][264]
    float* xs = Wb + 128 * EA_WB_STRIDE;     // [128 row][132]
    float* bb = xs + 128 * EA_XS_STRIDE;     // 256

    int tid = threadIdx.x;
    int row0 = blockIdx.x * 128;

    for (int i = tid; i < 128 * 32; i += 512) {
        int k = i >> 5, c = i & 31;
        float4 v = ((const float4*)(W_e + k * 128))[c];
        *(float4*)(Wb + k * EA_WB_STRIDE + 4 * c) = f2tf4(v);
    }
    for (int i = tid; i < 128 * 32; i += 512) {
        int k = i >> 5, c = i & 31;
        float4 v = ((const float4*)(W_a + k * 128))[c];
        *(float4*)(Wb + k * EA_WB_STRIDE + 128 + 4 * c) = f2tf4(v);
    }
    if (tid < 256) bb[tid] = (tid < 128) ? b_e[tid] : b_a[tid - 128];
    for (int i = tid; i < 128 * 32; i += 512) {
        int r = i >> 5, c = i & 31;
        int row = row0 + r;
        float4 v = make_float4(0.f, 0.f, 0.f, 0.f);
        if (row < NQA1) v = ((const float4*)(qa_table + (long)row * DVz))[c];
        *(float4*)(xs + r * EA_XS_STRIDE + 4 * c) = f2tf4(v);
    }
    __syncthreads();

    int warp = tid >> 5, lane = tid & 31;
    int G = lane >> 2, T = lane & 3;
    int rowb = (warp >> 2) * 32;
    int nb   = (warp & 3) * 64;

    float d[2][8][4];
#pragma unroll
    for (int mf = 0; mf < 2; mf++)
#pragma unroll
        for (int nf = 0; nf < 8; nf++)
#pragma unroll
            for (int j = 0; j < 4; j++) d[mf][nf][j] = 0.0f;

#pragma unroll 1
    for (int k0 = 0; k0 < 128; k0 += 8) {
        unsigned a[2][4];
#pragma unroll
        for (int mf = 0; mf < 2; mf++) {
            int r = rowb + mf * 16;
            a[mf][0] = __float_as_uint(xs[(r + G)     * EA_XS_STRIDE + k0 + T]);
            a[mf][1] = __float_as_uint(xs[(r + G + 8) * EA_XS_STRIDE + k0 + T]);
            a[mf][2] = __float_as_uint(xs[(r + G)     * EA_XS_STRIDE + k0 + T + 4]);
            a[mf][3] = __float_as_uint(xs[(r + G + 8) * EA_XS_STRIDE + k0 + T + 4]);
        }
#pragma unroll
        for (int nf = 0; nf < 8; nf++) {
            unsigned b[2];
            int n = nb + nf * 8 + G;
            b[0] = __float_as_uint(Wb[(k0 + T)     * EA_WB_STRIDE + n]);
            b[1] = __float_as_uint(Wb[(k0 + T + 4) * EA_WB_STRIDE + n]);
            mma8(d[0][nf], a[0], b);
            mma8(d[1][nf], a[1], b);
        }
    }

    __syncthreads();
    float* eo = Wb;

#pragma unroll
    for (int mf = 0; mf < 2; mf++) {
#pragma unroll
        for (int nf = 0; nf < 8; nf++) {
            int c = nb + nf * 8 + 2 * T;
            int r = rowb + mf * 16 + G;
#pragma unroll
            for (int h = 0; h < 2; h++) {
                int rr = r + 8 * h;
#pragma unroll
                for (int cc = 0; cc < 2; cc++) {
                    int col = c + cc;
                    float v = d[mf][nf][2 * h + cc] + bb[col];
                    v = (col < 128) ? (1.0f / (1.0f + __expf(-v))) : tanhf(v);
                    eo[rr * EA_WB_STRIDE + col] = v;
                }
            }
        }
    }
    __syncthreads();

    for (int i = tid; i < 128 * 64; i += 512) {
        int r = i >> 6, j = i & 63;
        int row = row0 + r;
        if (row < NQA1) {
            float2 e01 = *(const float2*)(eo + r * EA_WB_STRIDE + 2 * j);
            float2 a01 = *(const float2*)(eo + r * EA_WB_STRIDE + 128 + 2 * j);
            *(float4*)(&g_ea[(long)row * DVz + 2 * j]) =
                make_float4(e01.x, a01.x, e01.y, a01.y);
        }
    }
}

// ---------------------------------------------------------------------------
// Scan v3: 128 blocks x 1024 threads. tid = half*512 + d*4 + mh.
// Each thread owns 8 slot-pairs (mh*8 .. mh*8+7) of 32 padded pairs
// (25 real + 7 zero -> zero pairs are algebraic no-ops, no masking).
// 4 LDS.128 per step; mh-reduction via shfl_xor 1,2 (lanes 4-adjacent).
__global__ void __launch_bounds__(1024) k_scan(const int* __restrict__ q_data,
                                               const int* __restrict__ qa_data,
                                               const float* __restrict__ init_value) {
    __shared__ __align__(16) float w_s[32][3][WST];   // per-warp triple buffer
    __shared__ int qi_s[2][Sz], qa_s[2][Sz];

    int tid  = threadIdx.x;
    int half = tid >> 9;          // batch within block
    int sub  = tid & 511;
    int d    = sub >> 2;          // DV column
    int mh   = sub & 3;           // slot quarter
    int warp = tid >> 5;
    int lane = tid & 31;
    int p0   = mh * 8;            // first owned pair

    int b = blockIdx.x * 2 + half;
    int base = b * Sz;

    if (sub < Sz) {
        qi_s[half][sub] = q_data[base + sub];
        qa_s[half][sub] = qa_data[base + sub];
    }

    u64 mem[8];
#pragma unroll
    for (int i = 0; i < 8; i++) {
        int gp = p0 + i;
        if (gp < 25)
            mem[i] = pack2(init_value[(2*gp) * DVz + d],
                           init_value[(2*gp+1) * DVz + d]);
        else
            mem[i] = 0ull;
    }
    __syncthreads();

    // prime steps 0,1 (per-warp staging: 16 lanes x float4 = 64 floats)
    if (lane < 16) {
        ((float4*)w_s[warp][0])[lane] =
            ((const float4*)(g_w + qi_s[half][0] * WST))[lane];
        ((float4*)w_s[warp][1])[lane] =
            ((const float4*)(g_w + qi_s[half][1] * WST))[lane];
    }
    float2 ea0 = g_ea[qa_s[half][0] * DVz + d];
    float2 ea1 = g_ea[qa_s[half][1] * DVz + d];
    __syncwarp();

    int buf = 0;
    for (int s = 0; s < Sz; s++) {
        bool flag = (qi_s[half][s] >= 1);

        float2 ea2 = make_float2(0.f, 0.f);
        if (s + 2 < Sz) {
            ea2 = g_ea[qa_s[half][s + 2] * DVz + d];
            if (lane < 16) {
                int nb = buf + 2; if (nb >= 3) nb -= 3;
                ((float4*)w_s[warp][nb])[lane] =
                    ((const float4*)(g_w + qi_s[half][s + 2] * WST))[lane];
            }
        }

        u64 ne = pack2(ea0.x, ea0.x) ^ 0x8000000080000000ull;   // (-e,-e)
        u64 av = pack2(ea0.y, ea0.y);

        // read: 4 LDS.128 over owned 8 pairs
        const ulonglong2* wv = (const ulonglong2*)w_s[warp][buf] + mh * 4;
        u64 wr[8];
        u64 r0 = 0ull, r1 = 0ull, r2 = 0ull, r3 = 0ull;
        {
            ulonglong2 t0 = wv[0], t1 = wv[1], t2 = wv[2], t3 = wv[3];
            wr[0] = t0.x; r0 = fma2(t0.x, mem[0], r0);
            wr[1] = t0.y; r1 = fma2(t0.y, mem[1], r1);
            wr[2] = t1.x; r2 = fma2(t1.x, mem[2], r2);
            wr[3] = t1.y; r3 = fma2(t1.y, mem[3], r3);
            wr[4] = t2.x; r0 = fma2(t2.x, mem[4], r0);
            wr[5] = t2.y; r1 = fma2(t2.y, mem[5], r1);
            wr[6] = t3.x; r2 = fma2(t3.x, mem[6], r2);
            wr[7] = t3.y; r3 = fma2(t3.y, mem[7], r3);
        }
        u64 rr = add2(add2(r0, r1), add2(r2, r3));
        float lo, hi;
        unpack2(rr, lo, hi);
        float part = lo + hi;
        part += __shfl_xor_sync(0xffffffffu, part, 1);
        part += __shfl_xor_sync(0xffffffffu, part, 2);
        if (mh == 0) g_reads[(long)(base + s) * DVz + d] = part;

        // update (zero pairs stay zero: fma2(0, t, 0) = 0)
        if (flag) {
#pragma unroll
            for (int p = 0; p < 8; p++) {
                u64 t = fma2(ne, mem[p], av);
                mem[p] = fma2(wr[p], t, mem[p]);
            }
        }

        ea0 = ea1; ea1 = ea2;
        __syncwarp();
        buf += 1; if (buf == 3) buf = 0;
    }
}

// ---------------------------------------------------------------------------
// Head via tf32 mma (R12, unchanged): 64 rows/block, 256 thr, 2 blocks/SM.
#define HD_ROWS 64
#define HD_GRID (NROWS / HD_ROWS)
#define HD_XS_STRIDE 132
#define HD_WS_STRIDE 136
#define HEAD_SMEM_FLOATS (128*HD_WS_STRIDE + HD_ROWS*HD_XS_STRIDE + 128 + 128 + HD_ROWS + 2 + HD_ROWS)
__global__ void __launch_bounds__(256) k_head(const int* __restrict__ q_data,
                       const float* __restrict__ target,
                       const float* __restrict__ W_read, const float* __restrict__ b_read,
                       const float* __restrict__ W_pred, const float* __restrict__ b_pred,
                       float* __restrict__ out) {
    extern __shared__ float sm[];
    float* Ws = sm;                            // [128 k][136]
    float* xs = Ws + 128 * HD_WS_STRIDE;       // [64 row][132]
    float* wp = xs + HD_ROWS * HD_XS_STRIDE;   // 128
    float* br = wp + 128;                      // 128
    float* lo = br + 128;                      // 64
    float* ls = lo + HD_ROWS;                  // 2
    int*   qis = (int*)(ls + 2);               // 64

    int tid = threadIdx.x;
    int row0 = blockIdx.x * HD_ROWS;

    if (tid < HD_ROWS) qis[tid] = q_data[row0 + tid];
    if (tid < 2)   ls[tid] = 0.0f;
    float bp = __ldg(b_pred);
    if (tid < 128) { wp[tid] = W_pred[tid]; br[tid] = b_read[tid]; }
    if (tid < HD_ROWS) lo[tid] = bp;

    for (int i = tid; i < 128 * 32; i += 256) {
        int k = i >> 5, c = i & 31;
        float4 v = ((const float4*)(W_read + k * 128))[c];
        *(float4*)(Ws + k * HD_WS_STRIDE + 4 * c) = f2tf4(v);
    }
    for (int i = tid; i < HD_ROWS * 32; i += 256) {
        int r = i >> 5, c = i & 31;
        float4 v = ((const float4*)(g_reads + (long)(row0 + r) * DVz))[c];
        *(float4*)(xs + r * HD_XS_STRIDE + 4 * c) = f2tf4(v);
    }
    __syncthreads();

    int warp = tid >> 5, lane = tid & 31;
    int G = lane >> 2, T = lane & 3;
    int rowb = (warp >> 2) * 32;
    int nb   = (warp & 3) * 32;

    float d[2][4][4];
#pragma unroll
    for (int mf = 0; mf < 2; mf++)
#pragma unroll
        for (int nf = 0; nf < 4; nf++)
#pragma unroll
            for (int j = 0; j < 4; j++) d[mf][nf][j] = 0.0f;

#pragma unroll 2
    for (int k0 = 0; k0 < 128; k0 += 8) {
        unsigned a[2][4];
#pragma unroll
        for (int mf = 0; mf < 2; mf++) {
            int r = rowb + mf * 16;
            a[mf][0] = __float_as_uint(xs[(r + G)     * HD_XS_STRIDE + k0 + T]);
            a[mf][1] = __float_as_uint(xs[(r + G + 8) * HD_XS_STRIDE + k0 + T]);
            a[mf][2] = __float_as_uint(xs[(r + G)     * HD_XS_STRIDE + k0 + T + 4]);
            a[mf][3] = __float_as_uint(xs[(r + G + 8) * HD_XS_STRIDE + k0 + T + 4]);
        }
#pragma unroll
        for (int nf = 0; nf < 4; nf++) {
            unsigned b[2];
            int n = nb + nf * 8 + G;
            b[0] = __float_as_uint(Ws[(k0 + T)     * HD_WS_STRIDE + n]);
            b[1] = __float_as_uint(Ws[(k0 + T + 4) * HD_WS_STRIDE + n]);
            mma8(d[0][nf], a[0], b);
            mma8(d[1][nf], a[1], b);
        }
    }

#pragma unroll
    for (int mf = 0; mf < 2; mf++) {
#pragma unroll
        for (int h = 0; h < 2; h++) {
            int r = rowb + mf * 16 + G + 8 * h;
            const float* qr = g_qr + (long)qis[r] * Fz;
            float p = 0.0f;
#pragma unroll
            for (int nf = 0; nf < 4; nf++) {
                int c = nb + nf * 8 + 2 * T;
                float v0 = d[mf][nf][2*h + 0] + qr[c]     + br[c];
                float v1 = d[mf][nf][2*h + 1] + qr[c + 1] + br[c + 1];
                p = fmaf(tanhf(v0), wp[c],     p);
                p = fmaf(tanhf(v1), wp[c + 1], p);
            }
            p += __shfl_xor_sync(0xffffffffu, p, 1);
            p += __shfl_xor_sync(0xffffffffu, p, 2);
            if (T == 0) atomicAdd(&lo[r], p);
        }
    }
    __syncthreads();

    if (tid < HD_ROWS) {
        int row = row0 + tid;
        float l = lo[tid];
        float prob = 1.0f / (1.0f + __expf(-l));
        out[1 + row] = prob;
        float tt = target[row];
        float bce = 0.0f, cnt = 0.0f;
        if (tt >= 0.0f) {
            bce = fmaxf(l, 0.0f) - l * tt + log1pf(__expf(-fabsf(l)));
            cnt = 1.0f;
        }
#pragma unroll
        for (int off = 16; off >= 1; off >>= 1) {
            bce += __shfl_down_sync(0xffffffffu, bce, off);
            cnt += __shfl_down_sync(0xffffffffu, cnt, off);
        }
        if ((tid & 31) == 0) {
            atomicAdd(&ls[0], bce);
            atomicAdd(&ls[1], cnt);
        }
    }
    __syncthreads();
    if (tid == 0) {
        atomicAdd(&g_acc[0], ls[0]);
        atomicAdd(&g_acc[1], ls[1]);
        __threadfence();
        int done = atomicAdd(&g_done, 1);
        if (done == HD_GRID - 1) {
            __threadfence();
            out[0] = g_acc[0] / fmaxf(g_acc[1], 1.0f);
        }
    }
}

// ---------------------------------------------------------------------------
extern "C" void kernel_launch(void* const* d_in, const int* in_sizes, int n_in,
                              void* d_out, int out_size) {
    const int*   q_data    = (const int*)d_in[0];
    const int*   qa_data   = (const int*)d_in[1];
    const float* target    = (const float*)d_in[2];
    const float* q_table   = (const float*)d_in[3];
    const float* qa_table  = (const float*)d_in[4];
    const float* key_mem   = (const float*)d_in[5];
    const float* init_value= (const float*)d_in[6];
    const float* W_e    = (const float*)d_in[7];
    const float* b_e    = (const float*)d_in[8];
    const float* W_a    = (const float*)d_in[9];
    const float* b_a    = (const float*)d_in[10];
    const float* W_read = (const float*)d_in[11];
    const float* b_read = (const float*)d_in[12];
    const float* W_pred = (const float*)d_in[13];
    const float* b_pred = (const float*)d_in[14];
    float* out = (float*)d_out;

    size_t qr_smem   = QR_SMEM_FLOATS * sizeof(float);
    size_t ea_smem   = EA_SMEM_FLOATS * sizeof(float);
    size_t head_smem = HEAD_SMEM_FLOATS * sizeof(float);

    cudaFuncSetAttribute(k_qr,   cudaFuncAttributeMaxDynamicSharedMemorySize, (int)qr_smem);
    cudaFuncSetAttribute(k_ea,   cudaFuncAttributeMaxDynamicSharedMemorySize, (int)ea_smem);
    cudaFuncSetAttribute(k_head, cudaFuncAttributeMaxDynamicSharedMemorySize, (int)head_smem);

    k_w<<<(NQ1 + 127) / 128, 128>>>(q_table, key_mem);
    k_qr<<<(NQ1 + QR_ROWS - 1) / QR_ROWS, 512, qr_smem>>>(q_table, W_read);
    k_ea<<<(NQA1 + 127) / 128, 512, ea_smem>>>(qa_table, W_e, b_e, W_a, b_a);
    k_scan<<<Bz / 2, 1024>>>(q_data, qa_data, init_value);
    k_head<<<HD_GRID, 256, head_smem>>>(
        q_data, target, W_read, b_read, W_pred, b_pred, out);
}

// round 14
// speedup vs baseline: 1.3759x; 1.3759x over previous
#include <cuda_runtime.h>
#include <math.h>

#define Bz 256
#define Sz 256
#define Mz 50
#define MP 25
#define WST 64
#define DQz 64
#define DVz 128
#define Fz 128
#define NQ1 10001
#define NQA1 20001
#define NROWS (Bz*Sz)

typedef unsigned long long u64;

// ---- packed f32x2 helpers ---------------------------------------------------
__device__ __forceinline__ u64 pack2(float lo, float hi) {
    u64 r; asm("mov.b64 %0, {%1, %2};" : "=l"(r) : "f"(lo), "f"(hi)); return r;
}
__device__ __forceinline__ void unpack2(u64 v, float& lo, float& hi) {
    asm("mov.b64 {%0, %1}, %2;" : "=f"(lo), "=f"(hi) : "l"(v));
}
__device__ __forceinline__ u64 fma2(u64 a, u64 b, u64 c) {
    u64 d; asm("fma.rn.f32x2 %0, %1, %2, %3;" : "=l"(d) : "l"(a), "l"(b), "l"(c)); return d;
}
__device__ __forceinline__ u64 add2(u64 a, u64 b) {
    u64 d; asm("add.rn.f32x2 %0, %1, %2;" : "=l"(d) : "l"(a), "l"(b)); return d;
}

// ---- tf32 mma helpers ---------------------------------------------------------
__device__ __forceinline__ float f2tf(float f) {
    unsigned r; asm("cvt.rna.tf32.f32 %0, %1;" : "=r"(r) : "f"(f));
    return __uint_as_float(r);
}
__device__ __forceinline__ float4 f2tf4(float4 v) {
    return make_float4(f2tf(v.x), f2tf(v.y), f2tf(v.z), f2tf(v.w));
}
__device__ __forceinline__ void mma8(float* d, const unsigned* a, const unsigned* b) {
    asm volatile(
        "mma.sync.aligned.m16n8k8.row.col.f32.tf32.tf32.f32 "
        "{%0,%1,%2,%3}, {%4,%5,%6,%7}, {%8,%9}, {%0,%1,%2,%3};"
        : "+f"(d[0]), "+f"(d[1]), "+f"(d[2]), "+f"(d[3])
        : "r"(a[0]), "r"(a[1]), "r"(a[2]), "r"(a[3]), "r"(b[0]), "r"(b[1]));
}

// Scratch
__device__ float  g_w[NQ1 * WST];
__device__ float2 g_ea[NQA1 * DVz];
__device__ float  g_qr[NQ1 * Fz];
__device__ float  g_reads[NROWS * DVz];
__device__ float  g_acc[2];
__device__ int    g_done;

// ---------------------------------------------------------------------------
__global__ void __launch_bounds__(128) k_w(const float* __restrict__ q_table,
                                           const float* __restrict__ key_mem) {
    __shared__ float key_s[Mz * DQz];
    int tid = threadIdx.x;
    if (blockIdx.x == 0 && tid < 3) {
        if (tid < 2) g_acc[tid] = 0.0f;
        else g_done = 0;
    }
    for (int i = tid; i < Mz * DQz; i += 128) key_s[i] = key_mem[i];
    __syncthreads();

    int row = blockIdx.x * 128 + tid;
    if (row >= NQ1) return;

    float q[DQz];
    const float4* qp = (const float4*)(q_table + (long)row * DQz);
#pragma unroll
    for (int i = 0; i < DQz / 4; i++) {
        float4 v = qp[i];
        q[4*i+0] = v.x; q[4*i+1] = v.y; q[4*i+2] = v.z; q[4*i+3] = v.w;
    }

    float sc[Mz];
    float mx = -1e30f;
#pragma unroll
    for (int m = 0; m < Mz; m++) {
        float s = 0.0f;
#pragma unroll
        for (int k = 0; k < DQz; k++) s = fmaf(q[k], key_s[m * DQz + k], s);
        sc[m] = s;
        mx = fmaxf(mx, s);
    }
    float sum = 0.0f;
#pragma unroll
    for (int m = 0; m < Mz; m++) {
        float e = __expf(sc[m] - mx);
        sc[m] = e;
        sum += e;
    }
    float inv = 1.0f / sum;
#pragma unroll
    for (int m = 0; m < Mz; m++) g_w[row * WST + m] = sc[m] * inv;
#pragma unroll
    for (int m = Mz; m < WST; m++) g_w[row * WST + m] = 0.0f;
}

// ---------------------------------------------------------------------------
#define QR_ROWS 64
#define QR_SMEM_FLOATS (64*128 + QR_ROWS*DQz)
__global__ void __launch_bounds__(512) k_qr(const float* __restrict__ q_table,
                                            const float* __restrict__ W_read) {
    extern __shared__ float sm[];
    float* W2 = sm;
    float* xs = W2 + 64 * 128;

    int tid = threadIdx.x;
    for (int i = tid; i < 64 * 128 / 4; i += 512)
        ((float4*)W2)[i] = ((const float4*)(W_read + 128 * 128))[i];

    int row0 = blockIdx.x * QR_ROWS;
    for (int idx = tid; idx < QR_ROWS * 16; idx += 512) {
        int r = idx >> 4, c = idx & 15;
        int row = row0 + r;
        float4 v = make_float4(0.f, 0.f, 0.f, 0.f);
        if (row < NQ1) v = ((const float4*)(q_table + (long)row * DQz))[c];
        ((float4*)xs)[r * 16 + c] = v;
    }
    __syncthreads();

    int rg = tid >> 4;
    int fg = tid & 15;
    u64 acc[2][4];
#pragma unroll
    for (int r = 0; r < 2; r++)
#pragma unroll
        for (int j = 0; j < 4; j++) acc[r][j] = 0ull;

#pragma unroll 4
    for (int k = 0; k < 64; k++) {
        const ulonglong2* wv = (const ulonglong2*)(W2 + k * 128 + fg * 8);
        ulonglong2 w01 = wv[0], w23 = wv[1];
#pragma unroll
        for (int r = 0; r < 2; r++) {
            float xv = xs[(rg * 2 + r) * DQz + k];
            u64 xp = pack2(xv, xv);
            acc[r][0] = fma2(xp, w01.x, acc[r][0]);
            acc[r][1] = fma2(xp, w01.y, acc[r][1]);
            acc[r][2] = fma2(xp, w23.x, acc[r][2]);
            acc[r][3] = fma2(xp, w23.y, acc[r][3]);
        }
    }

#pragma unroll
    for (int r = 0; r < 2; r++) {
        int row = row0 + rg * 2 + r;
        if (row < NQ1) {
            float v[8];
#pragma unroll
            for (int j = 0; j < 4; j++) unpack2(acc[r][j], v[2*j], v[2*j+1]);
            float4* op = (float4*)(g_qr + (long)row * Fz + fg * 8);
            op[0] = make_float4(v[0], v[1], v[2], v[3]);
            op[1] = make_float4(v[4], v[5], v[6], v[7]);
        }
    }
}

// ---------------------------------------------------------------------------
// ea via tf32 mma (R12, unchanged). 128 rows/block, 512 thr, grid 157.
#define EA_XS_STRIDE 132
#define EA_WB_STRIDE 264
#define EA_SMEM_FLOATS (128*EA_WB_STRIDE + 128*EA_XS_STRIDE + 256)
__global__ void __launch_bounds__(512) k_ea(const float* __restrict__ qa_table,
                     const float* __restrict__ W_e, const float* __restrict__ b_e,
                     const float* __restrict__ W_a, const float* __restrict__ b_a) {
    extern __shared__ float sm[];
    float* Wb = sm;                          // [128 k][264]
    float* xs = Wb + 128 * EA_WB_STRIDE;     // [128 row][132]
    float* bb = xs + 128 * EA_XS_STRIDE;     // 256

    int tid = threadIdx.x;
    int row0 = blockIdx.x * 128;

    for (int i = tid; i < 128 * 32; i += 512) {
        int k = i >> 5, c = i & 31;
        float4 v = ((const float4*)(W_e + k * 128))[c];
        *(float4*)(Wb + k * EA_WB_STRIDE + 4 * c) = f2tf4(v);
    }
    for (int i = tid; i < 128 * 32; i += 512) {
        int k = i >> 5, c = i & 31;
        float4 v = ((const float4*)(W_a + k * 128))[c];
        *(float4*)(Wb + k * EA_WB_STRIDE + 128 + 4 * c) = f2tf4(v);
    }
    if (tid < 256) bb[tid] = (tid < 128) ? b_e[tid] : b_a[tid - 128];
    for (int i = tid; i < 128 * 32; i += 512) {
        int r = i >> 5, c = i & 31;
        int row = row0 + r;
        float4 v = make_float4(0.f, 0.f, 0.f, 0.f);
        if (row < NQA1) v = ((const float4*)(qa_table + (long)row * DVz))[c];
        *(float4*)(xs + r * EA_XS_STRIDE + 4 * c) = f2tf4(v);
    }
    __syncthreads();

    int warp = tid >> 5, lane = tid & 31;
    int G = lane >> 2, T = lane & 3;
    int rowb = (warp >> 2) * 32;
    int nb   = (warp & 3) * 64;

    float d[2][8][4];
#pragma unroll
    for (int mf = 0; mf < 2; mf++)
#pragma unroll
        for (int nf = 0; nf < 8; nf++)
#pragma unroll
            for (int j = 0; j < 4; j++) d[mf][nf][j] = 0.0f;

#pragma unroll 1
    for (int k0 = 0; k0 < 128; k0 += 8) {
        unsigned a[2][4];
#pragma unroll
        for (int mf = 0; mf < 2; mf++) {
            int r = rowb + mf * 16;
            a[mf][0] = __float_as_uint(xs[(r + G)     * EA_XS_STRIDE + k0 + T]);
            a[mf][1] = __float_as_uint(xs[(r + G + 8) * EA_XS_STRIDE + k0 + T]);
            a[mf][2] = __float_as_uint(xs[(r + G)     * EA_XS_STRIDE + k0 + T + 4]);
            a[mf][3] = __float_as_uint(xs[(r + G + 8) * EA_XS_STRIDE + k0 + T + 4]);
        }
#pragma unroll
        for (int nf = 0; nf < 8; nf++) {
            unsigned b[2];
            int n = nb + nf * 8 + G;
            b[0] = __float_as_uint(Wb[(k0 + T)     * EA_WB_STRIDE + n]);
            b[1] = __float_as_uint(Wb[(k0 + T + 4) * EA_WB_STRIDE + n]);
            mma8(d[0][nf], a[0], b);
            mma8(d[1][nf], a[1], b);
        }
    }

    __syncthreads();
    float* eo = Wb;

#pragma unroll
    for (int mf = 0; mf < 2; mf++) {
#pragma unroll
        for (int nf = 0; nf < 8; nf++) {
            int c = nb + nf * 8 + 2 * T;
            int r = rowb + mf * 16 + G;
#pragma unroll
            for (int h = 0; h < 2; h++) {
                int rr = r + 8 * h;
#pragma unroll
                for (int cc = 0; cc < 2; cc++) {
                    int col = c + cc;
                    float v = d[mf][nf][2 * h + cc] + bb[col];
                    v = (col < 128) ? (1.0f / (1.0f + __expf(-v))) : tanhf(v);
                    eo[rr * EA_WB_STRIDE + col] = v;
                }
            }
        }
    }
    __syncthreads();

    for (int i = tid; i < 128 * 64; i += 512) {
        int r = i >> 6, j = i & 63;
        int row = row0 + r;
        if (row < NQA1) {
            float2 e01 = *(const float2*)(eo + r * EA_WB_STRIDE + 2 * j);
            float2 a01 = *(const float2*)(eo + r * EA_WB_STRIDE + 128 + 2 * j);
            *(float4*)(&g_ea[(long)row * DVz + 2 * j]) =
                make_float4(e01.x, a01.x, e01.y, a01.y);
        }
    }
}

// ---------------------------------------------------------------------------
// Scan (R11-exact best-measured): 128 blocks x 256 thr, 2 batches/block,
// thread owns full d-column (25 pairs), warp-private w, 2-deep prefetch.
__global__ void __launch_bounds__(256) k_scan(const int* __restrict__ q_data,
                                              const int* __restrict__ qa_data,
                                              const float* __restrict__ init_value) {
    __shared__ __align__(16) float w_s[8][3][56];
    __shared__ int qi_s[2][Sz], qa_s[2][Sz];

    int tid  = threadIdx.x;
    int half = tid >> 7;
    int d    = tid & 127;
    int warp = tid >> 5;
    int lane = tid & 31;

    int b = blockIdx.x * 2 + half;
    int base = b * Sz;

    for (int i = d; i < Sz; i += 128) {
        qi_s[half][i] = q_data[base + i];
        qa_s[half][i] = qa_data[base + i];
    }

    u64 mem[MP];
#pragma unroll
    for (int p = 0; p < MP; p++)
        mem[p] = pack2(init_value[(2*p) * DVz + d], init_value[(2*p+1) * DVz + d]);
    __syncthreads();

    if (lane < 13) {
        ((float4*)w_s[warp][0])[lane] =
            ((const float4*)(g_w + qi_s[half][0] * WST))[lane];
        ((float4*)w_s[warp][1])[lane] =
            ((const float4*)(g_w + qi_s[half][1] * WST))[lane];
    }
    float2 ea0 = g_ea[qa_s[half][0] * DVz + d];
    float2 ea1 = g_ea[qa_s[half][1] * DVz + d];
    __syncwarp();

    int buf = 0;
    for (int s = 0; s < Sz; s++) {
        bool flag = (qi_s[half][s] >= 1);

        float2 ea2 = make_float2(0.f, 0.f);
        if (s + 2 < Sz) {
            ea2 = g_ea[qa_s[half][s + 2] * DVz + d];
            if (lane < 13) {
                int nb = buf + 2; if (nb >= 3) nb -= 3;
                ((float4*)w_s[warp][nb])[lane] =
                    ((const float4*)(g_w + qi_s[half][s + 2] * WST))[lane];
            }
        }

        u64 ne = pack2(ea0.x, ea0.x) ^ 0x8000000080000000ull;
        u64 av = pack2(ea0.y, ea0.y);

        const ulonglong2* wv = (const ulonglong2*)w_s[warp][buf];
        u64 wr[MP];
        u64 r0 = 0ull, r1 = 0ull, r2 = 0ull, r3 = 0ull;
#pragma unroll
        for (int i = 0; i < 12; i += 2) {
            ulonglong2 t0 = wv[i], t1 = wv[i + 1];
            wr[2*i+0] = t0.x; r0 = fma2(t0.x, mem[2*i+0], r0);
            wr[2*i+1] = t0.y; r1 = fma2(t0.y, mem[2*i+1], r1);
            wr[2*i+2] = t1.x; r2 = fma2(t1.x, mem[2*i+2], r2);
            wr[2*i+3] = t1.y; r3 = fma2(t1.y, mem[2*i+3], r3);
        }
        wr[24] = ((const u64*)w_s[warp][buf])[24];
        r0 = fma2(wr[24], mem[24], r0);
        u64 rr = add2(add2(r0, r1), add2(r2, r3));
        float lo, hi;
        unpack2(rr, lo, hi);
        g_reads[(long)(base + s) * DVz + d] = lo + hi;

        if (flag) {
#pragma unroll
            for (int p = 0; p < MP; p++) {
                u64 t = fma2(ne, mem[p], av);
                mem[p] = fma2(wr[p], t, mem[p]);
            }
        }

        ea0 = ea1; ea1 = ea2;
        __syncwarp();
        buf += 1; if (buf == 3) buf = 0;
    }
}

// ---------------------------------------------------------------------------
// Head via tf32 mma (R12, unchanged): 64 rows/block, 256 thr, 2 blocks/SM.
#define HD_ROWS 64
#define HD_GRID (NROWS / HD_ROWS)
#define HD_XS_STRIDE 132
#define HD_WS_STRIDE 136
#define HEAD_SMEM_FLOATS (128*HD_WS_STRIDE + HD_ROWS*HD_XS_STRIDE + 128 + 128 + HD_ROWS + 2 + HD_ROWS)
__global__ void __launch_bounds__(256) k_head(const int* __restrict__ q_data,
                       const float* __restrict__ target,
                       const float* __restrict__ W_read, const float* __restrict__ b_read,
                       const float* __restrict__ W_pred, const float* __restrict__ b_pred,
                       float* __restrict__ out) {
    extern __shared__ float sm[];
    float* Ws = sm;                            // [128 k][136]
    float* xs = Ws + 128 * HD_WS_STRIDE;       // [64 row][132]
    float* wp = xs + HD_ROWS * HD_XS_STRIDE;   // 128
    float* br = wp + 128;                      // 128
    float* lo = br + 128;                      // 64
    float* ls = lo + HD_ROWS;                  // 2
    int*   qis = (int*)(ls + 2);               // 64

    int tid = threadIdx.x;
    int row0 = blockIdx.x * HD_ROWS;

    if (tid < HD_ROWS) qis[tid] = q_data[row0 + tid];
    if (tid < 2)   ls[tid] = 0.0f;
    float bp = __ldg(b_pred);
    if (tid < 128) { wp[tid] = W_pred[tid]; br[tid] = b_read[tid]; }
    if (tid < HD_ROWS) lo[tid] = bp;

    for (int i = tid; i < 128 * 32; i += 256) {
        int k = i >> 5, c = i & 31;
        float4 v = ((const float4*)(W_read + k * 128))[c];
        *(float4*)(Ws + k * HD_WS_STRIDE + 4 * c) = f2tf4(v);
    }
    for (int i = tid; i < HD_ROWS * 32; i += 256) {
        int r = i >> 5, c = i & 31;
        float4 v = ((const float4*)(g_reads + (long)(row0 + r) * DVz))[c];
        *(float4*)(xs + r * HD_XS_STRIDE + 4 * c) = f2tf4(v);
    }
    __syncthreads();

    int warp = tid >> 5, lane = tid & 31;
    int G = lane >> 2, T = lane & 3;
    int rowb = (warp >> 2) * 32;
    int nb   = (warp & 3) * 32;

    float d[2][4][4];
#pragma unroll
    for (int mf = 0; mf < 2; mf++)
#pragma unroll
        for (int nf = 0; nf < 4; nf++)
#pragma unroll
            for (int j = 0; j < 4; j++) d[mf][nf][j] = 0.0f;

#pragma unroll 2
    for (int k0 = 0; k0 < 128; k0 += 8) {
        unsigned a[2][4];
#pragma unroll
        for (int mf = 0; mf < 2; mf++) {
            int r = rowb + mf * 16;
            a[mf][0] = __float_as_uint(xs[(r + G)     * HD_XS_STRIDE + k0 + T]);
            a[mf][1] = __float_as_uint(xs[(r + G + 8) * HD_XS_STRIDE + k0 + T]);
            a[mf][2] = __float_as_uint(xs[(r + G)     * HD_XS_STRIDE + k0 + T + 4]);
            a[mf][3] = __float_as_uint(xs[(r + G + 8) * HD_XS_STRIDE + k0 + T + 4]);
        }
#pragma unroll
        for (int nf = 0; nf < 4; nf++) {
            unsigned b[2];
            int n = nb + nf * 8 + G;
            b[0] = __float_as_uint(Ws[(k0 + T)     * HD_WS_STRIDE + n]);
            b[1] = __float_as_uint(Ws[(k0 + T + 4) * HD_WS_STRIDE + n]);
            mma8(d[0][nf], a[0], b);
            mma8(d[1][nf], a[1], b);
        }
    }

#pragma unroll
    for (int mf = 0; mf < 2; mf++) {
#pragma unroll
        for (int h = 0; h < 2; h++) {
            int r = rowb + mf * 16 + G + 8 * h;
            const float* qr = g_qr + (long)qis[r] * Fz;
            float p = 0.0f;
#pragma unroll
            for (int nf = 0; nf < 4; nf++) {
                int c = nb + nf * 8 + 2 * T;
                float v0 = d[mf][nf][2*h + 0] + qr[c]     + br[c];
                float v1 = d[mf][nf][2*h + 1] + qr[c + 1] + br[c + 1];
                p = fmaf(tanhf(v0), wp[c],     p);
                p = fmaf(tanhf(v1), wp[c + 1], p);
            }
            p += __shfl_xor_sync(0xffffffffu, p, 1);
            p += __shfl_xor_sync(0xffffffffu, p, 2);
            if (T == 0) atomicAdd(&lo[r], p);
        }
    }
    __syncthreads();

    if (tid < HD_ROWS) {
        int row = row0 + tid;
        float l = lo[tid];
        float prob = 1.0f / (1.0f + __expf(-l));
        out[1 + row] = prob;
        float tt = target[row];
        float bce = 0.0f, cnt = 0.0f;
        if (tt >= 0.0f) {
            bce = fmaxf(l, 0.0f) - l * tt + log1pf(__expf(-fabsf(l)));
            cnt = 1.0f;
        }
#pragma unroll
        for (int off = 16; off >= 1; off >>= 1) {
            bce += __shfl_down_sync(0xffffffffu, bce, off);
            cnt += __shfl_down_sync(0xffffffffu, cnt, off);
        }
        if ((tid & 31) == 0) {
            atomicAdd(&ls[0], bce);
            atomicAdd(&ls[1], cnt);
        }
    }
    __syncthreads();
    if (tid == 0) {
        atomicAdd(&g_acc[0], ls[0]);
        atomicAdd(&g_acc[1], ls[1]);
        __threadfence();
        int done = atomicAdd(&g_done, 1);
        if (done == HD_GRID - 1) {
            __threadfence();
            out[0] = g_acc[0] / fmaxf(g_acc[1], 1.0f);
        }
    }
}

// ---------------------------------------------------------------------------
extern "C" void kernel_launch(void* const* d_in, const int* in_sizes, int n_in,
                              void* d_out, int out_size) {
    const int*   q_data    = (const int*)d_in[0];
    const int*   qa_data   = (const int*)d_in[1];
    const float* target    = (const float*)d_in[2];
    const float* q_table   = (const float*)d_in[3];
    const float* qa_table  = (const float*)d_in[4];
    const float* key_mem   = (const float*)d_in[5];
    const float* init_value= (const float*)d_in[6];
    const float* W_e    = (const float*)d_in[7];
    const float* b_e    = (const float*)d_in[8];
    const float* W_a    = (const float*)d_in[9];
    const float* b_a    = (const float*)d_in[10];
    const float* W_read = (const float*)d_in[11];
    const float* b_read = (const float*)d_in[12];
    const float* W_pred = (const float*)d_in[13];
    const float* b_pred = (const float*)d_in[14];
    float* out = (float*)d_out;

    size_t qr_smem   = QR_SMEM_FLOATS * sizeof(float);
    size_t ea_smem   = EA_SMEM_FLOATS * sizeof(float);
    size_t head_smem = HEAD_SMEM_FLOATS * sizeof(float);

    cudaFuncSetAttribute(k_qr,   cudaFuncAttributeMaxDynamicSharedMemorySize, (int)qr_smem);
    cudaFuncSetAttribute(k_ea,   cudaFuncAttributeMaxDynamicSharedMemorySize, (int)ea_smem);
    cudaFuncSetAttribute(k_head, cudaFuncAttributeMaxDynamicSharedMemorySize, (int)head_smem);

    k_w<<<(NQ1 + 127) / 128, 128>>>(q_table, key_mem);
    k_qr<<<(NQ1 + QR_ROWS - 1) / QR_ROWS, 512, qr_smem>>>(q_table, W_read);
    k_ea<<<(NQA1 + 127) / 128, 512, ea_smem>>>(qa_table, W_e, b_e, W_a, b_a);
    k_scan<<<Bz / 2, 256>>>(q_data, qa_data, init_value);
    k_head<<<HD_GRID, 256, head_smem>>>(
        q_data, target, W_read, b_read, W_pred, b_pred, out);
}

// round 15
// speedup vs baseline: 1.4435x; 1.0492x over previous
#include <cuda_runtime.h>
#include <math.h>

#define Bz 256
#define Sz 256
#define Mz 50
#define MP 25
#define WST 64
#define DQz 64
#define DVz 128
#define Fz 128
#define NQ1 10001
#define NQA1 20001
#define NROWS (Bz*Sz)

typedef unsigned long long u64;

// ---- packed f32x2 helpers ---------------------------------------------------
__device__ __forceinline__ u64 pack2(float lo, float hi) {
    u64 r; asm("mov.b64 %0, {%1, %2};" : "=l"(r) : "f"(lo), "f"(hi)); return r;
}
__device__ __forceinline__ void unpack2(u64 v, float& lo, float& hi) {
    asm("mov.b64 {%0, %1}, %2;" : "=f"(lo), "=f"(hi) : "l"(v));
}
__device__ __forceinline__ u64 fma2(u64 a, u64 b, u64 c) {
    u64 d; asm("fma.rn.f32x2 %0, %1, %2, %3;" : "=l"(d) : "l"(a), "l"(b), "l"(c)); return d;
}
__device__ __forceinline__ u64 add2(u64 a, u64 b) {
    u64 d; asm("add.rn.f32x2 %0, %1, %2;" : "=l"(d) : "l"(a), "l"(b)); return d;
}

// ---- tf32 mma helpers ---------------------------------------------------------
__device__ __forceinline__ float f2tf(float f) {
    unsigned r; asm("cvt.rna.tf32.f32 %0, %1;" : "=r"(r) : "f"(f));
    return __uint_as_float(r);
}
__device__ __forceinline__ float4 f2tf4(float4 v) {
    return make_float4(f2tf(v.x), f2tf(v.y), f2tf(v.z), f2tf(v.w));
}
__device__ __forceinline__ void mma8(float* d, const unsigned* a, const unsigned* b) {
    asm volatile(
        "mma.sync.aligned.m16n8k8.row.col.f32.tf32.tf32.f32 "
        "{%0,%1,%2,%3}, {%4,%5,%6,%7}, {%8,%9}, {%0,%1,%2,%3};"
        : "+f"(d[0]), "+f"(d[1]), "+f"(d[2]), "+f"(d[3])
        : "r"(a[0]), "r"(a[1]), "r"(a[2]), "r"(a[3]), "r"(b[0]), "r"(b[1]));
}

// Scratch
__device__ float  g_w[NQ1 * WST];
__device__ float2 g_ea[NQA1 * DVz];
__device__ float  g_qr[NQ1 * Fz];
__device__ float  g_reads[NROWS * DVz];
__device__ float  g_acc[2];
__device__ int    g_done;

// ---------------------------------------------------------------------------
// Fused pre-pass (256 thr): blocks [0,40) -> softmax w table (one row/thread,
// f32x2 dot products); blocks [40,197) -> g_qr = q_table @ W_read[128:192].
#define PW_BLOCKS 40
#define PRE_GRID (PW_BLOCKS + 157)
#define PRE_SMEM_FLOATS (64*128 + 64*DQz)
__global__ void __launch_bounds__(256) k_pre(const float* __restrict__ q_table,
                                             const float* __restrict__ key_mem,
                                             const float* __restrict__ W_read) {
    extern __shared__ float sm[];
    int bid = blockIdx.x;
    int tid = threadIdx.x;

    if (bid == 0 && tid < 3) {
        if (tid < 2) g_acc[tid] = 0.0f;
        else g_done = 0;
    }

    if (bid < PW_BLOCKS) {
        // ---- softmax w table ----
        float* key_s = sm;   // 3200 floats, rows of 64 (256B-aligned)
        for (int i = tid; i < Mz * DQz; i += 256) key_s[i] = key_mem[i];
        __syncthreads();

        int row = bid * 256 + tid;
        if (row >= NQ1) return;

        u64 q2[32];
        const float4* qp = (const float4*)(q_table + (long)row * DQz);
#pragma unroll
        for (int i = 0; i < 16; i++) {
            float4 v = qp[i];
            q2[2*i+0] = pack2(v.x, v.y);
            q2[2*i+1] = pack2(v.z, v.w);
        }

        float sc[Mz];
        float mx = -1e30f;
#pragma unroll
        for (int m = 0; m < Mz; m++) {
            const u64* kp = (const u64*)(key_s + m * DQz);
            u64 a0 = 0ull, a1 = 0ull;
#pragma unroll
            for (int k = 0; k < 32; k += 2) {
                a0 = fma2(q2[k],     kp[k],     a0);
                a1 = fma2(q2[k + 1], kp[k + 1], a1);
            }
            float l0, h0, l1, h1;
            unpack2(a0, l0, h0);
            unpack2(a1, l1, h1);
            float s = (l0 + h0) + (l1 + h1);
            sc[m] = s;
            mx = fmaxf(mx, s);
        }
        float sum = 0.0f;
#pragma unroll
        for (int m = 0; m < Mz; m++) {
            float e = __expf(sc[m] - mx);
            sc[m] = e;
            sum += e;
        }
        float inv = 1.0f / sum;
#pragma unroll
        for (int m = 0; m < Mz; m++) g_w[row * WST + m] = sc[m] * inv;
#pragma unroll
        for (int m = Mz; m < WST; m++) g_w[row * WST + m] = 0.0f;
    } else {
        // ---- qr table ----
        float* W2 = sm;                  // 64 x 128
        float* xs = W2 + 64 * 128;       // 64 rows x 64

        for (int i = tid; i < 64 * 128 / 4; i += 256)
            ((float4*)W2)[i] = ((const float4*)(W_read + 128 * 128))[i];

        int row0 = (bid - PW_BLOCKS) * 64;
        for (int idx = tid; idx < 64 * 16; idx += 256) {
            int r = idx >> 4, c = idx & 15;
            int row = row0 + r;
            float4 v = make_float4(0.f, 0.f, 0.f, 0.f);
            if (row < NQ1) v = ((const float4*)(q_table + (long)row * DQz))[c];
            ((float4*)xs)[r * 16 + c] = v;
        }
        __syncthreads();

        int rg = tid >> 4;   // 16 groups x 4 rows
        int fg = tid & 15;   // 8 cols (4 packed pairs)
        u64 acc[4][4];
#pragma unroll
        for (int r = 0; r < 4; r++)
#pragma unroll
            for (int j = 0; j < 4; j++) acc[r][j] = 0ull;

#pragma unroll 4
        for (int k = 0; k < 64; k++) {
            const ulonglong2* wv = (const ulonglong2*)(W2 + k * 128 + fg * 8);
            ulonglong2 w01 = wv[0], w23 = wv[1];
#pragma unroll
            for (int r = 0; r < 4; r++) {
                float xv = xs[(rg * 4 + r) * DQz + k];
                u64 xp = pack2(xv, xv);
                acc[r][0] = fma2(xp, w01.x, acc[r][0]);
                acc[r][1] = fma2(xp, w01.y, acc[r][1]);
                acc[r][2] = fma2(xp, w23.x, acc[r][2]);
                acc[r][3] = fma2(xp, w23.y, acc[r][3]);
            }
        }

#pragma unroll
        for (int r = 0; r < 4; r++) {
            int row = row0 + rg * 4 + r;
            if (row < NQ1) {
                float v[8];
#pragma unroll
                for (int j = 0; j < 4; j++) unpack2(acc[r][j], v[2*j], v[2*j+1]);
                float4* op = (float4*)(g_qr + (long)row * Fz + fg * 8);
                op[0] = make_float4(v[0], v[1], v[2], v[3]);
                op[1] = make_float4(v[4], v[5], v[6], v[7]);
            }
        }
    }
}

// ---------------------------------------------------------------------------
// ea via tf32 mma: 160 rows/block, 640 thr (5 M-warps x 4 N-warps),
// grid 126 = ONE wave. smem ~215.5KB.
#define EA_ROWS 160
#define EA_THREADS 640
#define EA_GRID 126
#define EA_XS_STRIDE 132
#define EA_WB_STRIDE 264
#define EA_SMEM_FLOATS (128*EA_WB_STRIDE + EA_ROWS*EA_XS_STRIDE + 256)
__global__ void __launch_bounds__(EA_THREADS) k_ea(const float* __restrict__ qa_table,
                     const float* __restrict__ W_e, const float* __restrict__ b_e,
                     const float* __restrict__ W_a, const float* __restrict__ b_a) {
    extern __shared__ float sm[];
    float* Wb = sm;                          // [128 k][264]
    float* xs = Wb + 128 * EA_WB_STRIDE;     // [160 row][132]
    float* bb = xs + EA_ROWS * EA_XS_STRIDE; // 256

    int tid = threadIdx.x;
    int row0 = blockIdx.x * EA_ROWS;

    for (int i = tid; i < 128 * 32; i += EA_THREADS) {
        int k = i >> 5, c = i & 31;
        float4 v = ((const float4*)(W_e + k * 128))[c];
        *(float4*)(Wb + k * EA_WB_STRIDE + 4 * c) = f2tf4(v);
    }
    for (int i = tid; i < 128 * 32; i += EA_THREADS) {
        int k = i >> 5, c = i & 31;
        float4 v = ((const float4*)(W_a + k * 128))[c];
        *(float4*)(Wb + k * EA_WB_STRIDE + 128 + 4 * c) = f2tf4(v);
    }
    if (tid < 256) bb[tid] = (tid < 128) ? b_e[tid] : b_a[tid - 128];
    for (int i = tid; i < EA_ROWS * 32; i += EA_THREADS) {
        int r = i >> 5, c = i & 31;
        int row = row0 + r;
        float4 v = make_float4(0.f, 0.f, 0.f, 0.f);
        if (row < NQA1) v = ((const float4*)(qa_table + (long)row * DVz))[c];
        *(float4*)(xs + r * EA_XS_STRIDE + 4 * c) = f2tf4(v);
    }
    __syncthreads();

    int warp = tid >> 5, lane = tid & 31;
    int G = lane >> 2, T = lane & 3;
    int rowb = (warp >> 2) * 32;   // 5 M-groups: 0,32,64,96,128
    int nb   = (warp & 3) * 64;    // 4 N-groups

    float d[2][8][4];
#pragma unroll
    for (int mf = 0; mf < 2; mf++)
#pragma unroll
        for (int nf = 0; nf < 8; nf++)
#pragma unroll
            for (int j = 0; j < 4; j++) d[mf][nf][j] = 0.0f;

#pragma unroll 1
    for (int k0 = 0; k0 < 128; k0 += 8) {
        unsigned a[2][4];
#pragma unroll
        for (int mf = 0; mf < 2; mf++) {
            int r = rowb + mf * 16;
            a[mf][0] = __float_as_uint(xs[(r + G)     * EA_XS_STRIDE + k0 + T]);
            a[mf][1] = __float_as_uint(xs[(r + G + 8) * EA_XS_STRIDE + k0 + T]);
            a[mf][2] = __float_as_uint(xs[(r + G)     * EA_XS_STRIDE + k0 + T + 4]);
            a[mf][3] = __float_as_uint(xs[(r + G + 8) * EA_XS_STRIDE + k0 + T + 4]);
        }
#pragma unroll
        for (int nf = 0; nf < 8; nf++) {
            unsigned b[2];
            int n = nb + nf * 8 + G;
            b[0] = __float_as_uint(Wb[(k0 + T)     * EA_WB_STRIDE + n]);
            b[1] = __float_as_uint(Wb[(k0 + T + 4) * EA_WB_STRIDE + n]);
            mma8(d[0][nf], a[0], b);
            mma8(d[1][nf], a[1], b);
        }
    }

    __syncthreads();
    float* eo = sm;   // reuse: [160 row][264] = 42240 floats < 55K available

#pragma unroll
    for (int mf = 0; mf < 2; mf++) {
#pragma unroll
        for (int nf = 0; nf < 8; nf++) {
            int c = nb + nf * 8 + 2 * T;
            int r = rowb + mf * 16 + G;
#pragma unroll
            for (int h = 0; h < 2; h++) {
                int rr = r + 8 * h;
#pragma unroll
                for (int cc = 0; cc < 2; cc++) {
                    int col = c + cc;
                    float v = d[mf][nf][2 * h + cc] + bb[col];
                    v = (col < 128) ? (1.0f / (1.0f + __expf(-v))) : tanhf(v);
                    eo[rr * EA_WB_STRIDE + col] = v;
                }
            }
        }
    }
    __syncthreads();

    for (int i = tid; i < EA_ROWS * 64; i += EA_THREADS) {
        int r = i >> 6, j = i & 63;
        int row = row0 + r;
        if (row < NQA1) {
            float2 e01 = *(const float2*)(eo + r * EA_WB_STRIDE + 2 * j);
            float2 a01 = *(const float2*)(eo + r * EA_WB_STRIDE + 128 + 2 * j);
            *(float4*)(&g_ea[(long)row * DVz + 2 * j]) =
                make_float4(e01.x, a01.x, e01.y, a01.y);
        }
    }
}

// ---------------------------------------------------------------------------
// Scan: 128 blocks x 256 thr, 2 batches/block, warp-private w, 2-deep
// prefetch. Interleaved read+update (no wr[] array -> low register count).
__global__ void __launch_bounds__(256) k_scan(const int* __restrict__ q_data,
                                              const int* __restrict__ qa_data,
                                              const float* __restrict__ init_value) {
    __shared__ __align__(16) float w_s[8][3][56];
    __shared__ int qi_s[2][Sz], qa_s[2][Sz];

    int tid  = threadIdx.x;
    int half = tid >> 7;
    int d    = tid & 127;
    int warp = tid >> 5;
    int lane = tid & 31;

    int b = blockIdx.x * 2 + half;
    int base = b * Sz;

    for (int i = d; i < Sz; i += 128) {
        qi_s[half][i] = q_data[base + i];
        qa_s[half][i] = qa_data[base + i];
    }

    u64 mem[MP];
#pragma unroll
    for (int p = 0; p < MP; p++)
        mem[p] = pack2(init_value[(2*p) * DVz + d], init_value[(2*p+1) * DVz + d]);
    __syncthreads();

    if (lane < 13) {
        ((float4*)w_s[warp][0])[lane] =
            ((const float4*)(g_w + qi_s[half][0] * WST))[lane];
        ((float4*)w_s[warp][1])[lane] =
            ((const float4*)(g_w + qi_s[half][1] * WST))[lane];
    }
    float2 ea0 = g_ea[qa_s[half][0] * DVz + d];
    float2 ea1 = g_ea[qa_s[half][1] * DVz + d];
    __syncwarp();

    int buf = 0;
    for (int s = 0; s < Sz; s++) {
        bool flag = (qi_s[half][s] >= 1);

        float2 ea2 = make_float2(0.f, 0.f);
        if (s + 2 < Sz) {
            ea2 = g_ea[qa_s[half][s + 2] * DVz + d];
            if (lane < 13) {
                int nb = buf + 2; if (nb >= 3) nb -= 3;
                ((float4*)w_s[warp][nb])[lane] =
                    ((const float4*)(g_w + qi_s[half][s + 2] * WST))[lane];
            }
        }

        u64 ne = pack2(ea0.x, ea0.x) ^ 0x8000000080000000ull;
        u64 av = pack2(ea0.y, ea0.y);

        const ulonglong2* wv = (const ulonglong2*)w_s[warp][buf];
        u64 r0 = 0ull, r1 = 0ull, r2 = 0ull, r3 = 0ull;

        if (flag) {
#pragma unroll
            for (int i = 0; i < 12; i += 2) {
                ulonglong2 t0 = wv[i], t1 = wv[i + 1];
                r0 = fma2(t0.x, mem[2*i+0], r0);
                { u64 u = fma2(ne, mem[2*i+0], av); mem[2*i+0] = fma2(t0.x, u, mem[2*i+0]); }
                r1 = fma2(t0.y, mem[2*i+1], r1);
                { u64 u = fma2(ne, mem[2*i+1], av); mem[2*i+1] = fma2(t0.y, u, mem[2*i+1]); }
                r2 = fma2(t1.x, mem[2*i+2], r2);
                { u64 u = fma2(ne, mem[2*i+2], av); mem[2*i+2] = fma2(t1.x, u, mem[2*i+2]); }
                r3 = fma2(t1.y, mem[2*i+3], r3);
                { u64 u = fma2(ne, mem[2*i+3], av); mem[2*i+3] = fma2(t1.y, u, mem[2*i+3]); }
            }
            u64 w24 = ((const u64*)w_s[warp][buf])[24];
            r0 = fma2(w24, mem[24], r0);
            { u64 u = fma2(ne, mem[24], av); mem[24] = fma2(w24, u, mem[24]); }
        } else {
#pragma unroll
            for (int i = 0; i < 12; i += 2) {
                ulonglong2 t0 = wv[i], t1 = wv[i + 1];
                r0 = fma2(t0.x, mem[2*i+0], r0);
                r1 = fma2(t0.y, mem[2*i+1], r1);
                r2 = fma2(t1.x, mem[2*i+2], r2);
                r3 = fma2(t1.y, mem[2*i+3], r3);
            }
            u64 w24 = ((const u64*)w_s[warp][buf])[24];
            r0 = fma2(w24, mem[24], r0);
        }

        u64 rr = add2(add2(r0, r1), add2(r2, r3));
        float lo, hi;
        unpack2(rr, lo, hi);
        g_reads[(long)(base + s) * DVz + d] = lo + hi;

        ea0 = ea1; ea1 = ea2;
        __syncwarp();
        buf += 1; if (buf == 3) buf = 0;
    }
}

// ---------------------------------------------------------------------------
// Head via tf32 mma (R14, unchanged): 64 rows/block, 256 thr, 2 blocks/SM.
#define HD_ROWS 64
#define HD_GRID (NROWS / HD_ROWS)
#define HD_XS_STRIDE 132
#define HD_WS_STRIDE 136
#define HEAD_SMEM_FLOATS (128*HD_WS_STRIDE + HD_ROWS*HD_XS_STRIDE + 128 + 128 + HD_ROWS + 2 + HD_ROWS)
__global__ void __launch_bounds__(256) k_head(const int* __restrict__ q_data,
                       const float* __restrict__ target,
                       const float* __restrict__ W_read, const float* __restrict__ b_read,
                       const float* __restrict__ W_pred, const float* __restrict__ b_pred,
                       float* __restrict__ out) {
    extern __shared__ float sm[];
    float* Ws = sm;                            // [128 k][136]
    float* xs = Ws + 128 * HD_WS_STRIDE;       // [64 row][132]
    float* wp = xs + HD_ROWS * HD_XS_STRIDE;   // 128
    float* br = wp + 128;                      // 128
    float* lo = br + 128;                      // 64
    float* ls = lo + HD_ROWS;                  // 2
    int*   qis = (int*)(ls + 2);               // 64

    int tid = threadIdx.x;
    int row0 = blockIdx.x * HD_ROWS;

    if (tid < HD_ROWS) qis[tid] = q_data[row0 + tid];
    if (tid < 2)   ls[tid] = 0.0f;
    float bp = __ldg(b_pred);
    if (tid < 128) { wp[tid] = W_pred[tid]; br[tid] = b_read[tid]; }
    if (tid < HD_ROWS) lo[tid] = bp;

    for (int i = tid; i < 128 * 32; i += 256) {
        int k = i >> 5, c = i & 31;
        float4 v = ((const float4*)(W_read + k * 128))[c];
        *(float4*)(Ws + k * HD_WS_STRIDE + 4 * c) = f2tf4(v);
    }
    for (int i = tid; i < HD_ROWS * 32; i += 256) {
        int r = i >> 5, c = i & 31;
        float4 v = ((const float4*)(g_reads + (long)(row0 + r) * DVz))[c];
        *(float4*)(xs + r * HD_XS_STRIDE + 4 * c) = f2tf4(v);
    }
    __syncthreads();

    int warp = tid >> 5, lane = tid & 31;
    int G = lane >> 2, T = lane & 3;
    int rowb = (warp >> 2) * 32;
    int nb   = (warp & 3) * 32;

    float d[2][4][4];
#pragma unroll
    for (int mf = 0; mf < 2; mf++)
#pragma unroll
        for (int nf = 0; nf < 4; nf++)
#pragma unroll
            for (int j = 0; j < 4; j++) d[mf][nf][j] = 0.0f;

#pragma unroll 2
    for (int k0 = 0; k0 < 128; k0 += 8) {
        unsigned a[2][4];
#pragma unroll
        for (int mf = 0; mf < 2; mf++) {
            int r = rowb + mf * 16;
            a[mf][0] = __float_as_uint(xs[(r + G)     * HD_XS_STRIDE + k0 + T]);
            a[mf][1] = __float_as_uint(xs[(r + G + 8) * HD_XS_STRIDE + k0 + T]);
            a[mf][2] = __float_as_uint(xs[(r + G)     * HD_XS_STRIDE + k0 + T + 4]);
            a[mf][3] = __float_as_uint(xs[(r + G + 8) * HD_XS_STRIDE + k0 + T + 4]);
        }
#pragma unroll
        for (int nf = 0; nf < 4; nf++) {
            unsigned b[2];
            int n = nb + nf * 8 + G;
            b[0] = __float_as_uint(Ws[(k0 + T)     * HD_WS_STRIDE + n]);
            b[1] = __float_as_uint(Ws[(k0 + T + 4) * HD_WS_STRIDE + n]);
            mma8(d[0][nf], a[0], b);
            mma8(d[1][nf], a[1], b);
        }
    }

#pragma unroll
    for (int mf = 0; mf < 2; mf++) {
#pragma unroll
        for (int h = 0; h < 2; h++) {
            int r = rowb + mf * 16 + G + 8 * h;
            const float* qr = g_qr + (long)qis[r] * Fz;
            float p = 0.0f;
#pragma unroll
            for (int nf = 0; nf < 4; nf++) {
                int c = nb + nf * 8 + 2 * T;
                float v0 = d[mf][nf][2*h + 0] + qr[c]     + br[c];
                float v1 = d[mf][nf][2*h + 1] + qr[c + 1] + br[c + 1];
                p = fmaf(tanhf(v0), wp[c],     p);
                p = fmaf(tanhf(v1), wp[c + 1], p);
            }
            p += __shfl_xor_sync(0xffffffffu, p, 1);
            p += __shfl_xor_sync(0xffffffffu, p, 2);
            if (T == 0) atomicAdd(&lo[r], p);
        }
    }
    __syncthreads();

    if (tid < HD_ROWS) {
        int row = row0 + tid;
        float l = lo[tid];
        float prob = 1.0f / (1.0f + __expf(-l));
        out[1 + row] = prob;
        float tt = target[row];
        float bce = 0.0f, cnt = 0.0f;
        if (tt >= 0.0f) {
            bce = fmaxf(l, 0.0f) - l * tt + log1pf(__expf(-fabsf(l)));
            cnt = 1.0f;
        }
#pragma unroll
        for (int off = 16; off >= 1; off >>= 1) {
            bce += __shfl_down_sync(0xffffffffu, bce, off);
            cnt += __shfl_down_sync(0xffffffffu, cnt, off);
        }
        if ((tid & 31) == 0) {
            atomicAdd(&ls[0], bce);
            atomicAdd(&ls[1], cnt);
        }
    }
    __syncthreads();
    if (tid == 0) {
        atomicAdd(&g_acc[0], ls[0]);
        atomicAdd(&g_acc[1], ls[1]);
        __threadfence();
        int done = atomicAdd(&g_done, 1);
        if (done == HD_GRID - 1) {
            __threadfence();
            out[0] = g_acc[0] / fmaxf(g_acc[1], 1.0f);
        }
    }
}

// ---------------------------------------------------------------------------
extern "C" void kernel_launch(void* const* d_in, const int* in_sizes, int n_in,
                              void* d_out, int out_size) {
    const int*   q_data    = (const int*)d_in[0];
    const int*   qa_data   = (const int*)d_in[1];
    const float* target    = (const float*)d_in[2];
    const float* q_table   = (const float*)d_in[3];
    const float* qa_table  = (const float*)d_in[4];
    const float* key_mem   = (const float*)d_in[5];
    const float* init_value= (const float*)d_in[6];
    const float* W_e    = (const float*)d_in[7];
    const float* b_e    = (const float*)d_in[8];
    const float* W_a    = (const float*)d_in[9];
    const float* b_a    = (const float*)d_in[10];
    const float* W_read = (const float*)d_in[11];
    const float* b_read = (const float*)d_in[12];
    const float* W_pred = (const float*)d_in[13];
    const float* b_pred = (const float*)d_in[14];
    float* out = (float*)d_out;

    size_t pre_smem  = PRE_SMEM_FLOATS * sizeof(float);
    size_t ea_smem   = EA_SMEM_FLOATS * sizeof(float);
    size_t head_smem = HEAD_SMEM_FLOATS * sizeof(float);

    cudaFuncSetAttribute(k_pre,  cudaFuncAttributeMaxDynamicSharedMemorySize, (int)pre_smem);
    cudaFuncSetAttribute(k_ea,   cudaFuncAttributeMaxDynamicSharedMemorySize, (int)ea_smem);
    cudaFuncSetAttribute(k_head, cudaFuncAttributeMaxDynamicSharedMemorySize, (int)head_smem);

    k_pre<<<PRE_GRID, 256, pre_smem>>>(q_table, key_mem, W_read);
    k_ea<<<EA_GRID, EA_THREADS, ea_smem>>>(qa_table, W_e, b_e, W_a, b_a);
    k_scan<<<Bz / 2, 256>>>(q_data, qa_data, init_value);
    k_head<<<HD_GRID, 256, head_smem>>>(
        q_data, target, W_read, b_read, W_pred, b_pred, out);
}

// round 16
// speedup vs baseline: 1.4666x; 1.0160x over previous
#include <cuda_runtime.h>
#include <math.h>

#define Bz 256
#define Sz 256
#define Mz 50
#define MP 25
#define WST 64
#define DQz 64
#define DVz 128
#define Fz 128
#define NQ1 10001
#define NQA1 20001
#define NROWS (Bz*Sz)

typedef unsigned long long u64;

// ---- packed f32x2 helpers ---------------------------------------------------
__device__ __forceinline__ u64 pack2(float lo, float hi) {
    u64 r; asm("mov.b64 %0, {%1, %2};" : "=l"(r) : "f"(lo), "f"(hi)); return r;
}
__device__ __forceinline__ void unpack2(u64 v, float& lo, float& hi) {
    asm("mov.b64 {%0, %1}, %2;" : "=f"(lo), "=f"(hi) : "l"(v));
}
__device__ __forceinline__ u64 fma2(u64 a, u64 b, u64 c) {
    u64 d; asm("fma.rn.f32x2 %0, %1, %2, %3;" : "=l"(d) : "l"(a), "l"(b), "l"(c)); return d;
}
__device__ __forceinline__ u64 add2(u64 a, u64 b) {
    u64 d; asm("add.rn.f32x2 %0, %1, %2;" : "=l"(d) : "l"(a), "l"(b)); return d;
}

// ---- tf32 mma helpers ---------------------------------------------------------
__device__ __forceinline__ float f2tf(float f) {
    unsigned r; asm("cvt.rna.tf32.f32 %0, %1;" : "=r"(r) : "f"(f));
    return __uint_as_float(r);
}
__device__ __forceinline__ float4 f2tf4(float4 v) {
    return make_float4(f2tf(v.x), f2tf(v.y), f2tf(v.z), f2tf(v.w));
}
__device__ __forceinline__ void mma8(float* d, const unsigned* a, const unsigned* b) {
    asm volatile(
        "mma.sync.aligned.m16n8k8.row.col.f32.tf32.tf32.f32 "
        "{%0,%1,%2,%3}, {%4,%5,%6,%7}, {%8,%9}, {%0,%1,%2,%3};"
        : "+f"(d[0]), "+f"(d[1]), "+f"(d[2]), "+f"(d[3])
        : "r"(a[0]), "r"(a[1]), "r"(a[2]), "r"(a[3]), "r"(b[0]), "r"(b[1]));
}

// Scratch
__device__ float  g_w[NQ1 * WST];
__device__ float2 g_ea[NQA1 * DVz];
__device__ float  g_qr[NQ1 * Fz];
__device__ float  g_reads[NROWS * DVz];
__device__ float  g_acc[2];
__device__ int    g_done;

// ---------------------------------------------------------------------------
// Fused pre-pass (256 thr): blocks [0,40) -> softmax w; [40,197) -> g_qr.
#define PW_BLOCKS 40
#define PRE_GRID (PW_BLOCKS + 157)
#define PRE_SMEM_FLOATS (64*128 + 64*DQz)
__global__ void __launch_bounds__(256) k_pre(const float* __restrict__ q_table,
                                             const float* __restrict__ key_mem,
                                             const float* __restrict__ W_read) {
    extern __shared__ float sm[];
    int bid = blockIdx.x;
    int tid = threadIdx.x;

    if (bid == 0 && tid < 3) {
        if (tid < 2) g_acc[tid] = 0.0f;
        else g_done = 0;
    }

    if (bid < PW_BLOCKS) {
        float* key_s = sm;
        for (int i = tid; i < Mz * DQz; i += 256) key_s[i] = key_mem[i];
        __syncthreads();

        int row = bid * 256 + tid;
        if (row >= NQ1) return;

        u64 q2[32];
        const float4* qp = (const float4*)(q_table + (long)row * DQz);
#pragma unroll
        for (int i = 0; i < 16; i++) {
            float4 v = qp[i];
            q2[2*i+0] = pack2(v.x, v.y);
            q2[2*i+1] = pack2(v.z, v.w);
        }

        float sc[Mz];
        float mx = -1e30f;
#pragma unroll
        for (int m = 0; m < Mz; m++) {
            const u64* kp = (const u64*)(key_s + m * DQz);
            u64 a0 = 0ull, a1 = 0ull;
#pragma unroll
            for (int k = 0; k < 32; k += 2) {
                a0 = fma2(q2[k],     kp[k],     a0);
                a1 = fma2(q2[k + 1], kp[k + 1], a1);
            }
            float l0, h0, l1, h1;
            unpack2(a0, l0, h0);
            unpack2(a1, l1, h1);
            float s = (l0 + h0) + (l1 + h1);
            sc[m] = s;
            mx = fmaxf(mx, s);
        }
        float sum = 0.0f;
#pragma unroll
        for (int m = 0; m < Mz; m++) {
            float e = __expf(sc[m] - mx);
            sc[m] = e;
            sum += e;
        }
        float inv = 1.0f / sum;
#pragma unroll
        for (int m = 0; m < Mz; m++) g_w[row * WST + m] = sc[m] * inv;
#pragma unroll
        for (int m = Mz; m < WST; m++) g_w[row * WST + m] = 0.0f;
    } else {
        float* W2 = sm;                  // 64 x 128
        float* xs = W2 + 64 * 128;       // 64 rows x 64

        for (int i = tid; i < 64 * 128 / 4; i += 256)
            ((float4*)W2)[i] = ((const float4*)(W_read + 128 * 128))[i];

        int row0 = (bid - PW_BLOCKS) * 64;
        for (int idx = tid; idx < 64 * 16; idx += 256) {
            int r = idx >> 4, c = idx & 15;
            int row = row0 + r;
            float4 v = make_float4(0.f, 0.f, 0.f, 0.f);
            if (row < NQ1) v = ((const float4*)(q_table + (long)row * DQz))[c];
            ((float4*)xs)[r * 16 + c] = v;
        }
        __syncthreads();

        int rg = tid >> 4;
        int fg = tid & 15;
        u64 acc[4][4];
#pragma unroll
        for (int r = 0; r < 4; r++)
#pragma unroll
            for (int j = 0; j < 4; j++) acc[r][j] = 0ull;

#pragma unroll 4
        for (int k = 0; k < 64; k++) {
            const ulonglong2* wv = (const ulonglong2*)(W2 + k * 128 + fg * 8);
            ulonglong2 w01 = wv[0], w23 = wv[1];
#pragma unroll
            for (int r = 0; r < 4; r++) {
                float xv = xs[(rg * 4 + r) * DQz + k];
                u64 xp = pack2(xv, xv);
                acc[r][0] = fma2(xp, w01.x, acc[r][0]);
                acc[r][1] = fma2(xp, w01.y, acc[r][1]);
                acc[r][2] = fma2(xp, w23.x, acc[r][2]);
                acc[r][3] = fma2(xp, w23.y, acc[r][3]);
            }
        }

#pragma unroll
        for (int r = 0; r < 4; r++) {
            int row = row0 + rg * 4 + r;
            if (row < NQ1) {
                float v[8];
#pragma unroll
                for (int j = 0; j < 4; j++) unpack2(acc[r][j], v[2*j], v[2*j+1]);
                float4* op = (float4*)(g_qr + (long)row * Fz + fg * 8);
                op[0] = make_float4(v[0], v[1], v[2], v[3]);
                op[1] = make_float4(v[4], v[5], v[6], v[7]);
            }
        }
    }
}

// ---------------------------------------------------------------------------
// ea via tf32 mma (R15, unchanged): 160 rows/block, 640 thr, grid 126.
#define EA_ROWS 160
#define EA_THREADS 640
#define EA_GRID 126
#define EA_XS_STRIDE 132
#define EA_WB_STRIDE 264
#define EA_SMEM_FLOATS (128*EA_WB_STRIDE + EA_ROWS*EA_XS_STRIDE + 256)
__global__ void __launch_bounds__(EA_THREADS) k_ea(const float* __restrict__ qa_table,
                     const float* __restrict__ W_e, const float* __restrict__ b_e,
                     const float* __restrict__ W_a, const float* __restrict__ b_a) {
    extern __shared__ float sm[];
    float* Wb = sm;
    float* xs = Wb + 128 * EA_WB_STRIDE;
    float* bb = xs + EA_ROWS * EA_XS_STRIDE;

    int tid = threadIdx.x;
    int row0 = blockIdx.x * EA_ROWS;

    for (int i = tid; i < 128 * 32; i += EA_THREADS) {
        int k = i >> 5, c = i & 31;
        float4 v = ((const float4*)(W_e + k * 128))[c];
        *(float4*)(Wb + k * EA_WB_STRIDE + 4 * c) = f2tf4(v);
    }
    for (int i = tid; i < 128 * 32; i += EA_THREADS) {
        int k = i >> 5, c = i & 31;
        float4 v = ((const float4*)(W_a + k * 128))[c];
        *(float4*)(Wb + k * EA_WB_STRIDE + 128 + 4 * c) = f2tf4(v);
    }
    if (tid < 256) bb[tid] = (tid < 128) ? b_e[tid] : b_a[tid - 128];
    for (int i = tid; i < EA_ROWS * 32; i += EA_THREADS) {
        int r = i >> 5, c = i & 31;
        int row = row0 + r;
        float4 v = make_float4(0.f, 0.f, 0.f, 0.f);
        if (row < NQA1) v = ((const float4*)(qa_table + (long)row * DVz))[c];
        *(float4*)(xs + r * EA_XS_STRIDE + 4 * c) = f2tf4(v);
    }
    __syncthreads();

    int warp = tid >> 5, lane = tid & 31;
    int G = lane >> 2, T = lane & 3;
    int rowb = (warp >> 2) * 32;
    int nb   = (warp & 3) * 64;

    float d[2][8][4];
#pragma unroll
    for (int mf = 0; mf < 2; mf++)
#pragma unroll
        for (int nf = 0; nf < 8; nf++)
#pragma unroll
            for (int j = 0; j < 4; j++) d[mf][nf][j] = 0.0f;

#pragma unroll 1
    for (int k0 = 0; k0 < 128; k0 += 8) {
        unsigned a[2][4];
#pragma unroll
        for (int mf = 0; mf < 2; mf++) {
            int r = rowb + mf * 16;
            a[mf][0] = __float_as_uint(xs[(r + G)     * EA_XS_STRIDE + k0 + T]);
            a[mf][1] = __float_as_uint(xs[(r + G + 8) * EA_XS_STRIDE + k0 + T]);
            a[mf][2] = __float_as_uint(xs[(r + G)     * EA_XS_STRIDE + k0 + T + 4]);
            a[mf][3] = __float_as_uint(xs[(r + G + 8) * EA_XS_STRIDE + k0 + T + 4]);
        }
#pragma unroll
        for (int nf = 0; nf < 8; nf++) {
            unsigned b[2];
            int n = nb + nf * 8 + G;
            b[0] = __float_as_uint(Wb[(k0 + T)     * EA_WB_STRIDE + n]);
            b[1] = __float_as_uint(Wb[(k0 + T + 4) * EA_WB_STRIDE + n]);
            mma8(d[0][nf], a[0], b);
            mma8(d[1][nf], a[1], b);
        }
    }

    __syncthreads();
    float* eo = sm;

#pragma unroll
    for (int mf = 0; mf < 2; mf++) {
#pragma unroll
        for (int nf = 0; nf < 8; nf++) {
            int c = nb + nf * 8 + 2 * T;
            int r = rowb + mf * 16 + G;
#pragma unroll
            for (int h = 0; h < 2; h++) {
                int rr = r + 8 * h;
#pragma unroll
                for (int cc = 0; cc < 2; cc++) {
                    int col = c + cc;
                    float v = d[mf][nf][2 * h + cc] + bb[col];
                    v = (col < 128) ? (1.0f / (1.0f + __expf(-v))) : tanhf(v);
                    eo[rr * EA_WB_STRIDE + col] = v;
                }
            }
        }
    }
    __syncthreads();

    for (int i = tid; i < EA_ROWS * 64; i += EA_THREADS) {
        int r = i >> 6, j = i & 63;
        int row = row0 + r;
        if (row < NQA1) {
            float2 e01 = *(const float2*)(eo + r * EA_WB_STRIDE + 2 * j);
            float2 a01 = *(const float2*)(eo + r * EA_WB_STRIDE + 128 + 2 * j);
            *(float4*)(&g_ea[(long)row * DVz + 2 * j]) =
                make_float4(e01.x, a01.x, e01.y, a01.y);
        }
    }
}

// ---------------------------------------------------------------------------
// Scan (R15, unchanged): 128 blocks x 256 thr, interleaved read+update.
__global__ void __launch_bounds__(256) k_scan(const int* __restrict__ q_data,
                                              const int* __restrict__ qa_data,
                                              const float* __restrict__ init_value) {
    __shared__ __align__(16) float w_s[8][3][56];
    __shared__ int qi_s[2][Sz], qa_s[2][Sz];

    int tid  = threadIdx.x;
    int half = tid >> 7;
    int d    = tid & 127;
    int warp = tid >> 5;
    int lane = tid & 31;

    int b = blockIdx.x * 2 + half;
    int base = b * Sz;

    for (int i = d; i < Sz; i += 128) {
        qi_s[half][i] = q_data[base + i];
        qa_s[half][i] = qa_data[base + i];
    }

    u64 mem[MP];
#pragma unroll
    for (int p = 0; p < MP; p++)
        mem[p] = pack2(init_value[(2*p) * DVz + d], init_value[(2*p+1) * DVz + d]);
    __syncthreads();

    if (lane < 13) {
        ((float4*)w_s[warp][0])[lane] =
            ((const float4*)(g_w + qi_s[half][0] * WST))[lane];
        ((float4*)w_s[warp][1])[lane] =
            ((const float4*)(g_w + qi_s[half][1] * WST))[lane];
    }
    float2 ea0 = g_ea[qa_s[half][0] * DVz + d];
    float2 ea1 = g_ea[qa_s[half][1] * DVz + d];
    __syncwarp();

    int buf = 0;
    for (int s = 0; s < Sz; s++) {
        bool flag = (qi_s[half][s] >= 1);

        float2 ea2 = make_float2(0.f, 0.f);
        if (s + 2 < Sz) {
            ea2 = g_ea[qa_s[half][s + 2] * DVz + d];
            if (lane < 13) {
                int nb = buf + 2; if (nb >= 3) nb -= 3;
                ((float4*)w_s[warp][nb])[lane] =
                    ((const float4*)(g_w + qi_s[half][s + 2] * WST))[lane];
            }
        }

        u64 ne = pack2(ea0.x, ea0.x) ^ 0x8000000080000000ull;
        u64 av = pack2(ea0.y, ea0.y);

        const ulonglong2* wv = (const ulonglong2*)w_s[warp][buf];
        u64 r0 = 0ull, r1 = 0ull, r2 = 0ull, r3 = 0ull;

        if (flag) {
#pragma unroll
            for (int i = 0; i < 12; i += 2) {
                ulonglong2 t0 = wv[i], t1 = wv[i + 1];
                r0 = fma2(t0.x, mem[2*i+0], r0);
                { u64 u = fma2(ne, mem[2*i+0], av); mem[2*i+0] = fma2(t0.x, u, mem[2*i+0]); }
                r1 = fma2(t0.y, mem[2*i+1], r1);
                { u64 u = fma2(ne, mem[2*i+1], av); mem[2*i+1] = fma2(t0.y, u, mem[2*i+1]); }
                r2 = fma2(t1.x, mem[2*i+2], r2);
                { u64 u = fma2(ne, mem[2*i+2], av); mem[2*i+2] = fma2(t1.x, u, mem[2*i+2]); }
                r3 = fma2(t1.y, mem[2*i+3], r3);
                { u64 u = fma2(ne, mem[2*i+3], av); mem[2*i+3] = fma2(t1.y, u, mem[2*i+3]); }
            }
            u64 w24 = ((const u64*)w_s[warp][buf])[24];
            r0 = fma2(w24, mem[24], r0);
            { u64 u = fma2(ne, mem[24], av); mem[24] = fma2(w24, u, mem[24]); }
        } else {
#pragma unroll
            for (int i = 0; i < 12; i += 2) {
                ulonglong2 t0 = wv[i], t1 = wv[i + 1];
                r0 = fma2(t0.x, mem[2*i+0], r0);
                r1 = fma2(t0.y, mem[2*i+1], r1);
                r2 = fma2(t1.x, mem[2*i+2], r2);
                r3 = fma2(t1.y, mem[2*i+3], r3);
            }
            u64 w24 = ((const u64*)w_s[warp][buf])[24];
            r0 = fma2(w24, mem[24], r0);
        }

        u64 rr = add2(add2(r0, r1), add2(r2, r3));
        float lo, hi;
        unpack2(rr, lo, hi);
        g_reads[(long)(base + s) * DVz + d] = lo + hi;

        ea0 = ea1; ea1 = ea2;
        __syncwarp();
        buf += 1; if (buf == 3) buf = 0;
    }
}

// ---------------------------------------------------------------------------
// Head via tf32 mma: 128 rows/block, 512 thr (16 warps = 4M x 4N), grid 512.
// W staging amortized 2x vs R15; 16 warps/SM for latency hiding.
#define HD_ROWS 128
#define HD_GRID (NROWS / HD_ROWS)
#define HD_XS_STRIDE 132
#define HD_WS_STRIDE 136
#define HEAD_SMEM_FLOATS (128*HD_WS_STRIDE + HD_ROWS*HD_XS_STRIDE + 128 + 128 + HD_ROWS + 2 + HD_ROWS)
__global__ void __launch_bounds__(512) k_head(const int* __restrict__ q_data,
                       const float* __restrict__ target,
                       const float* __restrict__ W_read, const float* __restrict__ b_read,
                       const float* __restrict__ W_pred, const float* __restrict__ b_pred,
                       float* __restrict__ out) {
    extern __shared__ float sm[];
    float* Ws = sm;                            // [128 k][136]
    float* xs = Ws + 128 * HD_WS_STRIDE;       // [128 row][132]
    float* wp = xs + HD_ROWS * HD_XS_STRIDE;   // 128
    float* br = wp + 128;                      // 128
    float* lo = br + 128;                      // 128
    float* ls = lo + HD_ROWS;                  // 2
    int*   qis = (int*)(ls + 2);               // 128

    int tid = threadIdx.x;
    int row0 = blockIdx.x * HD_ROWS;

    if (tid < HD_ROWS) qis[tid] = q_data[row0 + tid];
    if (tid < 2)   ls[tid] = 0.0f;
    float bp = __ldg(b_pred);
    if (tid < 128) { wp[tid] = W_pred[tid]; br[tid] = b_read[tid]; }
    if (tid < HD_ROWS) lo[tid] = bp;

    for (int i = tid; i < 128 * 32; i += 512) {
        int k = i >> 5, c = i & 31;
        float4 v = ((const float4*)(W_read + k * 128))[c];
        *(float4*)(Ws + k * HD_WS_STRIDE + 4 * c) = f2tf4(v);
    }
    for (int i = tid; i < HD_ROWS * 32; i += 512) {
        int r = i >> 5, c = i & 31;
        float4 v = ((const float4*)(g_reads + (long)(row0 + r) * DVz))[c];
        *(float4*)(xs + r * HD_XS_STRIDE + 4 * c) = f2tf4(v);
    }
    __syncthreads();

    int warp = tid >> 5, lane = tid & 31;
    int G = lane >> 2, T = lane & 3;
    int rowb = (warp >> 2) * 32;   // 4 M-groups x 32 rows = 128
    int nb   = (warp & 3) * 32;    // 4 N-groups x 32 cols = 128

    float d[2][4][4];
#pragma unroll
    for (int mf = 0; mf < 2; mf++)
#pragma unroll
        for (int nf = 0; nf < 4; nf++)
#pragma unroll
            for (int j = 0; j < 4; j++) d[mf][nf][j] = 0.0f;

#pragma unroll 2
    for (int k0 = 0; k0 < 128; k0 += 8) {
        unsigned a[2][4];
#pragma unroll
        for (int mf = 0; mf < 2; mf++) {
            int r = rowb + mf * 16;
            a[mf][0] = __float_as_uint(xs[(r + G)     * HD_XS_STRIDE + k0 + T]);
            a[mf][1] = __float_as_uint(xs[(r + G + 8) * HD_XS_STRIDE + k0 + T]);
            a[mf][2] = __float_as_uint(xs[(r + G)     * HD_XS_STRIDE + k0 + T + 4]);
            a[mf][3] = __float_as_uint(xs[(r + G + 8) * HD_XS_STRIDE + k0 + T + 4]);
        }
#pragma unroll
        for (int nf = 0; nf < 4; nf++) {
            unsigned b[2];
            int n = nb + nf * 8 + G;
            b[0] = __float_as_uint(Ws[(k0 + T)     * HD_WS_STRIDE + n]);
            b[1] = __float_as_uint(Ws[(k0 + T + 4) * HD_WS_STRIDE + n]);
            mma8(d[0][nf], a[0], b);
            mma8(d[1][nf], a[1], b);
        }
    }

#pragma unroll
    for (int mf = 0; mf < 2; mf++) {
#pragma unroll
        for (int h = 0; h < 2; h++) {
            int r = rowb + mf * 16 + G + 8 * h;
            const float* qr = g_qr + (long)qis[r] * Fz;
            float p = 0.0f;
#pragma unroll
            for (int nf = 0; nf < 4; nf++) {
                int c = nb + nf * 8 + 2 * T;
                float v0 = d[mf][nf][2*h + 0] + qr[c]     + br[c];
                float v1 = d[mf][nf][2*h + 1] + qr[c + 1] + br[c + 1];
                p = fmaf(tanhf(v0), wp[c],     p);
                p = fmaf(tanhf(v1), wp[c + 1], p);
            }
            p += __shfl_xor_sync(0xffffffffu, p, 1);
            p += __shfl_xor_sync(0xffffffffu, p, 2);
            if (T == 0) atomicAdd(&lo[r], p);
        }
    }
    __syncthreads();

    if (tid < HD_ROWS) {
        int row = row0 + tid;
        float l = lo[tid];
        float prob = 1.0f / (1.0f + __expf(-l));
        out[1 + row] = prob;
        float tt = target[row];
        float bce = 0.0f, cnt = 0.0f;
        if (tt >= 0.0f) {
            bce = fmaxf(l, 0.0f) - l * tt + log1pf(__expf(-fabsf(l)));
            cnt = 1.0f;
        }
#pragma unroll
        for (int off = 16; off >= 1; off >>= 1) {
            bce += __shfl_down_sync(0xffffffffu, bce, off);
            cnt += __shfl_down_sync(0xffffffffu, cnt, off);
        }
        if ((tid & 31) == 0) {
            atomicAdd(&ls[0], bce);
            atomicAdd(&ls[1], cnt);
        }
    }
    __syncthreads();
    if (tid == 0) {
        atomicAdd(&g_acc[0], ls[0]);
        atomicAdd(&g_acc[1], ls[1]);
        __threadfence();
        int done = atomicAdd(&g_done, 1);
        if (done == HD_GRID - 1) {
            __threadfence();
            out[0] = g_acc[0] / fmaxf(g_acc[1], 1.0f);
        }
    }
}

// ---------------------------------------------------------------------------
extern "C" void kernel_launch(void* const* d_in, const int* in_sizes, int n_in,
                              void* d_out, int out_size) {
    const int*   q_data    = (const int*)d_in[0];
    const int*   qa_data   = (const int*)d_in[1];
    const float* target    = (const float*)d_in[2];
    const float* q_table   = (const float*)d_in[3];
    const float* qa_table  = (const float*)d_in[4];
    const float* key_mem   = (const float*)d_in[5];
    const float* init_value= (const float*)d_in[6];
    const float* W_e    = (const float*)d_in[7];
    const float* b_e    = (const float*)d_in[8];
    const float* W_a    = (const float*)d_in[9];
    const float* b_a    = (const float*)d_in[10];
    const float* W_read = (const float*)d_in[11];
    const float* b_read = (const float*)d_in[12];
    const float* W_pred = (const float*)d_in[13];
    const float* b_pred = (const float*)d_in[14];
    float* out = (float*)d_out;

    size_t pre_smem  = PRE_SMEM_FLOATS * sizeof(float);
    size_t ea_smem   = EA_SMEM_FLOATS * sizeof(float);
    size_t head_smem = HEAD_SMEM_FLOATS * sizeof(float);

    cudaFuncSetAttribute(k_pre,  cudaFuncAttributeMaxDynamicSharedMemorySize, (int)pre_smem);
    cudaFuncSetAttribute(k_ea,   cudaFuncAttributeMaxDynamicSharedMemorySize, (int)ea_smem);
    cudaFuncSetAttribute(k_head, cudaFuncAttributeMaxDynamicSharedMemorySize, (int)head_smem);

    k_pre<<<PRE_GRID, 256, pre_smem>>>(q_table, key_mem, W_read);
    k_ea<<<EA_GRID, EA_THREADS, ea_smem>>>(qa_table, W_e, b_e, W_a, b_a);
    k_scan<<<Bz / 2, 256>>>(q_data, qa_data, init_value);
    k_head<<<HD_GRID, 512, head_smem>>>(
        q_data, target, W_read, b_read, W_pred, b_pred, out);
}